// round 14
// baseline (speedup 1.0000x reference)
#include <cuda_runtime.h>
#include <cstdint>

// CharRNN on GB300 (sm_103a), round 13: 22 warps, perfectly balanced SMSPs.
// 128 blocks x 704 threads. Roles:
//   wid 0..9   REC layers 0..9            (8 rows, 512 ffma2/step-tick4)
//   wid 10..15 GEMM full layers 0..5
//   wid 18,19  GEMM full layers 8,9
//   wid 16,20  GEMM halves of layer 6 (rows 0-3 / 4-7)
//   wid 17,21  GEMM halves of layer 7
// SMSP loads (wid%4): SMSP0 {0,4,8,12,16,20} = 4 full + 2 half = 2560;
// SMSP1 {1,5,9,13,17,21} = 2560; SMSP2/3 = 5 full = 2560. Perfect balance,
// 6/6/5/5 warps. Everything else identical to R13 best (2 neurons/lane,
// 4 steps/tick, depth-8 h/z rings, one __syncthreads/tick, x prefetch).
// Plus: REC z-values hoisted before the FMA chain (hide their LDS latency).

#define NBLK  128
#define NTHR  704
#define ROWS  8
#define TT    1024
#define LL    10
#define HID   32
#define VOC   256
#define LST   36
#define RL    (ROWS*LST)
#define DEPTH 8
#define NTICK 275

typedef unsigned long long ull;

__device__ __forceinline__ void ffma2(ull &d, ull a, ull b) {
    asm("fma.rn.f32x2 %0, %1, %2, %0;" : "+l"(d) : "l"(a), "l"(b));
}
__device__ __forceinline__ float f2red(ull a) {
    float lo, hi;
    asm("mov.b64 {%0, %1}, %2;" : "=f"(lo), "=f"(hi) : "l"(a));
    return lo + hi;
}
__device__ __forceinline__ float tanh_fast(float x) {
    float e = __expf(2.0f * x);
    return 1.0f - __fdividef(2.0f, e + 1.0f);
}

__global__ void __launch_bounds__(NTHR, 1)
charrnn_kernel(const int*   __restrict__ x,
               const float* __restrict__ emb,
               const float* __restrict__ W_ih,
               const float* __restrict__ W_hh,
               const float* __restrict__ b_ih,
               const float* __restrict__ b_hh,
               const float* __restrict__ W_fc,
               const float* __restrict__ b_fc,
               float*       __restrict__ out)
{
    extern __shared__ float smem[];
    float* sh  = smem;                        // h rings [LL][DEPTH][ROWS][LST]
    float* sz  = smem + LL * DEPTH * RL;      // z rings [LL][DEPTH][ROWS][LST]
    float* sxs = sz   + LL * DEPTH * RL;      // GEMM_0 stage [4][ROWS][LST]

    const int tid  = threadIdx.x;
    const int wid  = tid >> 5;
    const int lane = tid & 31;
    const int row0 = blockIdx.x * ROWS;

    for (int i = tid; i < LL * DEPTH * RL; i += NTHR) sh[i] = 0.0f;

    // ---- role decode ----
    const bool isRec   = (wid < 10);
    const bool isHalfG = (wid >= 16 && wid != 18 && wid != 19);
    int l;
    if (isRec)              l = wid;
    else if (wid <= 15)     l = wid - 10;      // GEMM full 0..5
    else if (wid == 18)     l = 8;
    else if (wid == 19)     l = 9;
    else                    l = 6 + (wid & 1); // halves: 16,20 -> 6 ; 17,21 -> 7
    const int hrowbase = (wid >= 20) ? 4 : 0;  // half-GEMM row base

    float*       hown = sh + l * DEPTH * RL;
    const float* hup  = (l > 0) ? (sh + (l - 1) * DEPTH * RL) : sxs;
    float*       zl   = sz + l * DEPTH * RL;

    const int half = lane >> 4;
    const int rb   = half * 4;
    const int n0   = lane & 15;
    const int n1   = n0 + 16;

    if (isRec) {
        // ======================= REC warp: h = tanh(z + Whh.h) =======================
        ull whh0[16], whh1[16];
        {
            const ulonglong2* p = (const ulonglong2*)(W_hh + (l * HID + n0) * HID);
            #pragma unroll
            for (int q = 0; q < 8; ++q) { ulonglong2 v = p[q]; whh0[2*q] = v.x; whh0[2*q+1] = v.y; }
            p = (const ulonglong2*)(W_hh + (l * HID + n1) * HID);
            #pragma unroll
            for (int q = 0; q < 8; ++q) { ulonglong2 v = p[q]; whh1[2*q] = v.x; whh1[2*q+1] = v.y; }
        }
        __syncthreads();

        for (int v = 0; v < NTICK; ++v) {
            const int t0 = 4 * (v - 2 * l - 1);
            if (t0 >= 0 && t0 < TT) {
                #pragma unroll
                for (int st = 0; st < 4; ++st) {
                    const int t = t0 + st;
                    const float* hb   = hown + ((t - 1) & (DEPTH-1)) * RL;
                    const float* zrow = zl   + (t & (DEPTH-1)) * RL;
                    float*       ob   = hown + (t & (DEPTH-1)) * RL;

                    #pragma unroll
                    for (int g = 0; g < 2; ++g) {
                        const int rA = rb + 2*g;
                        const int rB = rA + 1;
                        // hoist z loads: issue before the FMA chain so their
                        // 29-cyc LDS latency hides under 64 ffma2 of issue
                        const float zA0 = zrow[rA * LST + n0];
                        const float zA1 = zrow[rA * LST + n1];
                        const float zB0 = zrow[rB * LST + n0];
                        const float zB1 = zrow[rB * LST + n1];
                        ull a00 = 0ull, a01 = 0ull, a10 = 0ull, a11 = 0ull;
                        #pragma unroll
                        for (int q = 0; q < 8; ++q) {
                            ulonglong2 vA = *(const ulonglong2*)(hb + rA * LST + q * 4);
                            ulonglong2 vB = *(const ulonglong2*)(hb + rB * LST + q * 4);
                            ffma2(a00, whh0[2*q], vA.x); ffma2(a00, whh0[2*q+1], vA.y);
                            ffma2(a01, whh1[2*q], vA.x); ffma2(a01, whh1[2*q+1], vA.y);
                            ffma2(a10, whh0[2*q], vB.x); ffma2(a10, whh0[2*q+1], vB.y);
                            ffma2(a11, whh1[2*q], vB.x); ffma2(a11, whh1[2*q+1], vB.y);
                        }
                        ob[rA * LST + n0] = tanh_fast(f2red(a00) + zA0);
                        ob[rA * LST + n1] = tanh_fast(f2red(a01) + zA1);
                        ob[rB * LST + n0] = tanh_fast(f2red(a10) + zB0);
                        ob[rB * LST + n1] = tanh_fast(f2red(a11) + zB1);
                    }
                    __syncwarp();
                }
            }
            __syncthreads();
        }
    } else if (!isHalfG) {
        // ======================= full GEMM warp: z = Wih.x + bias =======================
        ull wih0[16], wih1[16];
        {
            const ulonglong2* p = (const ulonglong2*)(W_ih + (l * HID + n0) * HID);
            #pragma unroll
            for (int q = 0; q < 8; ++q) { ulonglong2 v = p[q]; wih0[2*q] = v.x; wih0[2*q+1] = v.y; }
            p = (const ulonglong2*)(W_ih + (l * HID + n1) * HID);
            #pragma unroll
            for (int q = 0; q < 8; ++q) { ulonglong2 v = p[q]; wih1[2*q] = v.x; wih1[2*q+1] = v.y; }
        }
        const float bias0 = __ldg(&b_ih[l * HID + n0]) + __ldg(&b_hh[l * HID + n0]);
        const float bias1 = __ldg(&b_ih[l * HID + n1]) + __ldg(&b_hh[l * HID + n1]);

        int4 xi = make_int4(0, 0, 0, 0);
        if (l == 0 && lane < ROWS)
            xi = *(const int4*)(x + (row0 + lane) * TT);

        __syncthreads();

        for (int v = 0; v < NTICK; ++v) {
            const int t0 = 4 * (v - 2 * l);
            if (t0 >= 0 && t0 < TT) {
                if (l == 0) {
                    #pragma unroll
                    for (int r = 0; r < ROWS; ++r) {
                        const int ix = __shfl_sync(0xffffffffu, xi.x, r);
                        const int iy = __shfl_sync(0xffffffffu, xi.y, r);
                        const int iz = __shfl_sync(0xffffffffu, xi.z, r);
                        const int iw = __shfl_sync(0xffffffffu, xi.w, r);
                        sxs[0 * RL + r * LST + lane] = __ldg(&emb[ix * HID + lane]);
                        sxs[1 * RL + r * LST + lane] = __ldg(&emb[iy * HID + lane]);
                        sxs[2 * RL + r * LST + lane] = __ldg(&emb[iz * HID + lane]);
                        sxs[3 * RL + r * LST + lane] = __ldg(&emb[iw * HID + lane]);
                    }
                    if (lane < ROWS && t0 + 4 < TT)
                        xi = *(const int4*)(x + (row0 + lane) * TT + t0 + 4);
                    __syncwarp();
                }
                #pragma unroll
                for (int st = 0; st < 4; ++st) {
                    const int t = t0 + st;
                    const float* inb = (l == 0) ? (sxs + st * RL)
                                                : (hup + (t & (DEPTH-1)) * RL);
                    float* zo = zl + (t & (DEPTH-1)) * RL;

                    #pragma unroll
                    for (int g = 0; g < 2; ++g) {
                        const int rA = rb + 2*g;
                        const int rB = rA + 1;
                        ull a00 = 0ull, a01 = 0ull, a10 = 0ull, a11 = 0ull;
                        #pragma unroll
                        for (int q = 0; q < 8; ++q) {
                            ulonglong2 vA = *(const ulonglong2*)(inb + rA * LST + q * 4);
                            ulonglong2 vB = *(const ulonglong2*)(inb + rB * LST + q * 4);
                            ffma2(a00, wih0[2*q], vA.x); ffma2(a00, wih0[2*q+1], vA.y);
                            ffma2(a01, wih1[2*q], vA.x); ffma2(a01, wih1[2*q+1], vA.y);
                            ffma2(a10, wih0[2*q], vB.x); ffma2(a10, wih0[2*q+1], vB.y);
                            ffma2(a11, wih1[2*q], vB.x); ffma2(a11, wih1[2*q+1], vB.y);
                        }
                        zo[rA * LST + n0] = f2red(a00) + bias0;
                        zo[rA * LST + n1] = f2red(a01) + bias1;
                        zo[rB * LST + n0] = f2red(a10) + bias0;
                        zo[rB * LST + n1] = f2red(a11) + bias1;
                    }
                }
            }
            __syncthreads();
        }
    } else {
        // ======================= half GEMM warp (layers 6,7; 4 rows) =======================
        ull wih0[16], wih1[16];
        {
            const ulonglong2* p = (const ulonglong2*)(W_ih + (l * HID + n0) * HID);
            #pragma unroll
            for (int q = 0; q < 8; ++q) { ulonglong2 v = p[q]; wih0[2*q] = v.x; wih0[2*q+1] = v.y; }
            p = (const ulonglong2*)(W_ih + (l * HID + n1) * HID);
            #pragma unroll
            for (int q = 0; q < 8; ++q) { ulonglong2 v = p[q]; wih1[2*q] = v.x; wih1[2*q+1] = v.y; }
        }
        const float bias0 = __ldg(&b_ih[l * HID + n0]) + __ldg(&b_hh[l * HID + n0]);
        const float bias1 = __ldg(&b_ih[l * HID + n1]) + __ldg(&b_hh[l * HID + n1]);
        __syncthreads();

        // this warp's 2-row sub-half within its 4-row block
        const int rA0 = hrowbase + half * 2;
        const int rB0 = rA0 + 1;

        for (int v = 0; v < NTICK; ++v) {
            const int t0 = 4 * (v - 2 * l);
            if (t0 >= 0 && t0 < TT) {
                #pragma unroll
                for (int st = 0; st < 4; ++st) {
                    const int t = t0 + st;
                    const float* inb = hup + (t & (DEPTH-1)) * RL;
                    float* zo = zl + (t & (DEPTH-1)) * RL;

                    ull a00 = 0ull, a01 = 0ull, a10 = 0ull, a11 = 0ull;
                    #pragma unroll
                    for (int q = 0; q < 8; ++q) {
                        ulonglong2 vA = *(const ulonglong2*)(inb + rA0 * LST + q * 4);
                        ulonglong2 vB = *(const ulonglong2*)(inb + rB0 * LST + q * 4);
                        ffma2(a00, wih0[2*q], vA.x); ffma2(a00, wih0[2*q+1], vA.y);
                        ffma2(a01, wih1[2*q], vA.x); ffma2(a01, wih1[2*q+1], vA.y);
                        ffma2(a10, wih0[2*q], vB.x); ffma2(a10, wih0[2*q+1], vB.y);
                        ffma2(a11, wih1[2*q], vB.x); ffma2(a11, wih1[2*q+1], vB.y);
                    }
                    zo[rA0 * LST + n0] = f2red(a00) + bias0;
                    zo[rA0 * LST + n1] = f2red(a01) + bias1;
                    zo[rB0 * LST + n0] = f2red(a10) + bias0;
                    zo[rB0 * LST + n1] = f2red(a11) + bias1;
                }
            }
            __syncthreads();
        }
    }

    __syncthreads();

    // ---- final FC: out = h9(1023) @ W_fc^T + b_fc ; slot 1023&7 = 7 ----
    const float* h9 = sh + ((LL - 1) * DEPTH + 7) * RL;
    for (int i = tid; i < ROWS * VOC; i += NTHR) {
        const int r  = i >> 8;
        const int vv = i & (VOC - 1);
        const float4* wfc = (const float4*)(W_fc + vv * HID);
        const float*  hr  = h9 + r * LST;
        float sum = __ldg(&b_fc[vv]);
        #pragma unroll
        for (int q = 0; q < 8; ++q) {
            float4 aw = wfc[q];
            sum += aw.x * hr[q*4+0] + aw.y * hr[q*4+1] + aw.z * hr[q*4+2] + aw.w * hr[q*4+3];
        }
        out[(row0 + r) * VOC + vv] = sum;
    }
}

extern "C" void kernel_launch(void* const* d_in, const int* in_sizes, int n_in,
                              void* d_out, int out_size)
{
    const int*   x    = (const int*)  d_in[0];
    const float* emb  = (const float*)d_in[1];
    const float* W_ih = (const float*)d_in[2];
    const float* W_hh = (const float*)d_in[3];
    const float* b_ih = (const float*)d_in[4];
    const float* b_hh = (const float*)d_in[5];
    const float* W_fc = (const float*)d_in[6];
    const float* b_fc = (const float*)d_in[7];
    float* out = (float*)d_out;

    const int shbytes = (2 * LL * DEPTH + 4) * RL * (int)sizeof(float);  // 188928
    cudaFuncSetAttribute(charrnn_kernel,
                         cudaFuncAttributeMaxDynamicSharedMemorySize, shbytes);
    charrnn_kernel<<<NBLK, NTHR, shbytes>>>(x, emb, W_ih, W_hh, b_ih, b_hh,
                                            W_fc, b_fc, out);
}

// round 15
// speedup vs baseline: 1.0782x; 1.0782x over previous
#include <cuda_runtime.h>
#include <cstdint>

// CharRNN on GB300 (sm_103a), round 14 = R12 (best) + instruction diet.
// 128 blocks x 640 threads. wids 0..9 = REC layers, 10..19 = GEMM layers.
// Lane owns neurons (n0, n0+16) for its 4-row half; 4 steps/tick; depth-8
// h/z rings; one __syncthreads per tick; GEMM_0 x-index prefetch.
// Diet: (1) z stored as float2 pairs (n0,n1) -> 4 STS.64/LDS.64 per step
// instead of 8 scalar; (2) 5-op tanh (ex2/rcp/fma, same math as before);
// (3) REC hoists z loads ahead of the FMA chain.

#define NBLK  128
#define NTHR  640
#define ROWS  8
#define TT    1024
#define LL    10
#define HID   32
#define VOC   256
#define LST   36
#define RL    (ROWS*LST)
#define DEPTH 8
#define NTICK 275

typedef unsigned long long ull;

__device__ __forceinline__ void ffma2(ull &d, ull a, ull b) {
    asm("fma.rn.f32x2 %0, %1, %2, %0;" : "+l"(d) : "l"(a), "l"(b));
}
__device__ __forceinline__ float f2red(ull a) {
    float lo, hi;
    asm("mov.b64 {%0, %1}, %2;" : "=f"(lo), "=f"(hi) : "l"(a));
    return lo + hi;
}
// tanh(x) = 1 - 2/(exp(2x)+1), hand-scheduled: ex2(x*2log2e), rcp(e+1),
// fma(-2, r, 1). Same arithmetic path as __expf/__fdividef version.
__device__ __forceinline__ float tanh_fast(float x) {
    float e;
    asm("ex2.approx.f32 %0, %1;" : "=f"(e) : "f"(x * 2.885390082f));
    float r;
    asm("rcp.approx.f32 %0, %1;" : "=f"(r) : "f"(e + 1.0f));
    return fmaf(-2.0f, r, 1.0f);
}

__global__ void __launch_bounds__(NTHR, 1)
charrnn_kernel(const int*   __restrict__ x,
               const float* __restrict__ emb,
               const float* __restrict__ W_ih,
               const float* __restrict__ W_hh,
               const float* __restrict__ b_ih,
               const float* __restrict__ b_hh,
               const float* __restrict__ W_fc,
               const float* __restrict__ b_fc,
               float*       __restrict__ out)
{
    extern __shared__ float smem[];
    float* sh  = smem;                        // h rings [LL][DEPTH][ROWS][LST]
    float* sz  = smem + LL * DEPTH * RL;      // z rings (paired layout)
    float* sxs = sz   + LL * DEPTH * RL;      // GEMM_0 stage [4][ROWS][LST]

    const int tid  = threadIdx.x;
    const int wid  = tid >> 5;
    const int lane = tid & 31;
    const int row0 = blockIdx.x * ROWS;

    for (int i = tid; i < LL * DEPTH * RL; i += NTHR) sh[i] = 0.0f;

    const bool isRec = (wid < 10);
    const int  l     = isRec ? wid : (wid - 10);

    float*       hown = sh + l * DEPTH * RL;
    const float* hup  = (l > 0) ? (sh + (l - 1) * DEPTH * RL) : sxs;
    float*       zl   = sz + l * DEPTH * RL;

    const int half = lane >> 4;       // row half (0: rows 0-3, 1: rows 4-7)
    const int rb   = half * 4;
    const int n0   = lane & 15;       // owned neurons n0, n0+16
    const int n1   = n0 + 16;

    if (isRec) {
        // ======================= REC warp: h = tanh(z + Whh.h) =======================
        ull whh0[16], whh1[16];
        {
            const ulonglong2* p = (const ulonglong2*)(W_hh + (l * HID + n0) * HID);
            #pragma unroll
            for (int q = 0; q < 8; ++q) { ulonglong2 v = p[q]; whh0[2*q] = v.x; whh0[2*q+1] = v.y; }
            p = (const ulonglong2*)(W_hh + (l * HID + n1) * HID);
            #pragma unroll
            for (int q = 0; q < 8; ++q) { ulonglong2 v = p[q]; whh1[2*q] = v.x; whh1[2*q+1] = v.y; }
        }
        __syncthreads();

        for (int v = 0; v < NTICK; ++v) {
            const int t0 = 4 * (v - 2 * l - 1);
            if (t0 >= 0 && t0 < TT) {
                #pragma unroll
                for (int st = 0; st < 4; ++st) {
                    const int t = t0 + st;
                    const float* hb   = hown + ((t - 1) & (DEPTH-1)) * RL;
                    const float* zrow = zl   + (t & (DEPTH-1)) * RL;
                    float*       ob   = hown + (t & (DEPTH-1)) * RL;

                    #pragma unroll
                    for (int g = 0; g < 2; ++g) {
                        const int rA = rb + 2*g;
                        const int rB = rA + 1;
                        // hoisted paired z loads (latency hides under FMA chain)
                        const float2 zA = *(const float2*)(zrow + rA * LST + n0 * 2);
                        const float2 zB = *(const float2*)(zrow + rB * LST + n0 * 2);
                        ull a00 = 0ull, a01 = 0ull, a10 = 0ull, a11 = 0ull;
                        #pragma unroll
                        for (int q = 0; q < 8; ++q) {
                            ulonglong2 vA = *(const ulonglong2*)(hb + rA * LST + q * 4);
                            ulonglong2 vB = *(const ulonglong2*)(hb + rB * LST + q * 4);
                            ffma2(a00, whh0[2*q], vA.x); ffma2(a00, whh0[2*q+1], vA.y);
                            ffma2(a01, whh1[2*q], vA.x); ffma2(a01, whh1[2*q+1], vA.y);
                            ffma2(a10, whh0[2*q], vB.x); ffma2(a10, whh0[2*q+1], vB.y);
                            ffma2(a11, whh1[2*q], vB.x); ffma2(a11, whh1[2*q+1], vB.y);
                        }
                        ob[rA * LST + n0] = tanh_fast(f2red(a00) + zA.x);
                        ob[rA * LST + n1] = tanh_fast(f2red(a01) + zA.y);
                        ob[rB * LST + n0] = tanh_fast(f2red(a10) + zB.x);
                        ob[rB * LST + n1] = tanh_fast(f2red(a11) + zB.y);
                    }
                    __syncwarp();
                }
            }
            __syncthreads();
        }
    } else {
        // ======================= GEMM warp: z = Wih.x + bias =======================
        ull wih0[16], wih1[16];
        {
            const ulonglong2* p = (const ulonglong2*)(W_ih + (l * HID + n0) * HID);
            #pragma unroll
            for (int q = 0; q < 8; ++q) { ulonglong2 v = p[q]; wih0[2*q] = v.x; wih0[2*q+1] = v.y; }
            p = (const ulonglong2*)(W_ih + (l * HID + n1) * HID);
            #pragma unroll
            for (int q = 0; q < 8; ++q) { ulonglong2 v = p[q]; wih1[2*q] = v.x; wih1[2*q+1] = v.y; }
        }
        const float bias0 = __ldg(&b_ih[l * HID + n0]) + __ldg(&b_hh[l * HID + n0]);
        const float bias1 = __ldg(&b_ih[l * HID + n1]) + __ldg(&b_hh[l * HID + n1]);

        int4 xi = make_int4(0, 0, 0, 0);
        if (l == 0 && lane < ROWS)
            xi = *(const int4*)(x + (row0 + lane) * TT);

        __syncthreads();

        for (int v = 0; v < NTICK; ++v) {
            const int t0 = 4 * (v - 2 * l);
            if (t0 >= 0 && t0 < TT) {
                if (l == 0) {
                    #pragma unroll
                    for (int r = 0; r < ROWS; ++r) {
                        const int ix = __shfl_sync(0xffffffffu, xi.x, r);
                        const int iy = __shfl_sync(0xffffffffu, xi.y, r);
                        const int iz = __shfl_sync(0xffffffffu, xi.z, r);
                        const int iw = __shfl_sync(0xffffffffu, xi.w, r);
                        sxs[0 * RL + r * LST + lane] = __ldg(&emb[ix * HID + lane]);
                        sxs[1 * RL + r * LST + lane] = __ldg(&emb[iy * HID + lane]);
                        sxs[2 * RL + r * LST + lane] = __ldg(&emb[iz * HID + lane]);
                        sxs[3 * RL + r * LST + lane] = __ldg(&emb[iw * HID + lane]);
                    }
                    if (lane < ROWS && t0 + 4 < TT)
                        xi = *(const int4*)(x + (row0 + lane) * TT + t0 + 4);
                    __syncwarp();
                }
                #pragma unroll
                for (int st = 0; st < 4; ++st) {
                    const int t = t0 + st;
                    const float* inb = (l == 0) ? (sxs + st * RL)
                                                : (hup + (t & (DEPTH-1)) * RL);
                    float* zo = zl + (t & (DEPTH-1)) * RL;

                    #pragma unroll
                    for (int g = 0; g < 2; ++g) {
                        const int rA = rb + 2*g;
                        const int rB = rA + 1;
                        ull a00 = 0ull, a01 = 0ull, a10 = 0ull, a11 = 0ull;
                        #pragma unroll
                        for (int q = 0; q < 8; ++q) {
                            ulonglong2 vA = *(const ulonglong2*)(inb + rA * LST + q * 4);
                            ulonglong2 vB = *(const ulonglong2*)(inb + rB * LST + q * 4);
                            ffma2(a00, wih0[2*q], vA.x); ffma2(a00, wih0[2*q+1], vA.y);
                            ffma2(a01, wih1[2*q], vA.x); ffma2(a01, wih1[2*q+1], vA.y);
                            ffma2(a10, wih0[2*q], vB.x); ffma2(a10, wih0[2*q+1], vB.y);
                            ffma2(a11, wih1[2*q], vB.x); ffma2(a11, wih1[2*q+1], vB.y);
                        }
                        // paired z store: one STS.64 per row
                        *(float2*)(zo + rA * LST + n0 * 2) =
                            make_float2(f2red(a00) + bias0, f2red(a01) + bias1);
                        *(float2*)(zo + rB * LST + n0 * 2) =
                            make_float2(f2red(a10) + bias0, f2red(a11) + bias1);
                    }
                }
            }
            __syncthreads();
        }
    }

    __syncthreads();

    // ---- final FC: out = h9(1023) @ W_fc^T + b_fc ; slot 1023&7 = 7 ----
    const float* h9 = sh + ((LL - 1) * DEPTH + 7) * RL;
    for (int i = tid; i < ROWS * VOC; i += NTHR) {
        const int r  = i >> 8;
        const int vv = i & (VOC - 1);
        const float4* wfc = (const float4*)(W_fc + vv * HID);
        const float*  hr  = h9 + r * LST;
        float sum = __ldg(&b_fc[vv]);
        #pragma unroll
        for (int q = 0; q < 8; ++q) {
            float4 aw = wfc[q];
            sum += aw.x * hr[q*4+0] + aw.y * hr[q*4+1] + aw.z * hr[q*4+2] + aw.w * hr[q*4+3];
        }
        out[(row0 + r) * VOC + vv] = sum;
    }
}

extern "C" void kernel_launch(void* const* d_in, const int* in_sizes, int n_in,
                              void* d_out, int out_size)
{
    const int*   x    = (const int*)  d_in[0];
    const float* emb  = (const float*)d_in[1];
    const float* W_ih = (const float*)d_in[2];
    const float* W_hh = (const float*)d_in[3];
    const float* b_ih = (const float*)d_in[4];
    const float* b_hh = (const float*)d_in[5];
    const float* W_fc = (const float*)d_in[6];
    const float* b_fc = (const float*)d_in[7];
    float* out = (float*)d_out;

    const int shbytes = (2 * LL * DEPTH + 4) * RL * (int)sizeof(float);  // 188928
    cudaFuncSetAttribute(charrnn_kernel,
                         cudaFuncAttributeMaxDynamicSharedMemorySize, shbytes);
    charrnn_kernel<<<NBLK, NTHR, shbytes>>>(x, emb, W_ih, W_hh, b_ih, b_hh,
                                            W_fc, b_fc, out);
}

// round 16
// speedup vs baseline: 1.0859x; 1.0071x over previous
#include <cuda_runtime.h>
#include <cstdint>

// CharRNN on GB300 (sm_103a), round 15 = R12 (best, 1245us) + two safe cuts:
//   (1) 5-op tanh: ex2/fadd/rcp/fma (same math as __expf/__fdividef form).
//   (2) REC z-loads hoisted ahead of the whh FMA chain (pure reorder).
// Everything else identical to R12: 128 blocks x 640 threads, wids 0..9 REC /
// 10..19 GEMM, 2 neurons/lane x 4-row half, 4 steps/tick, depth-8 h/z rings,
// scalar z stores, one __syncthreads per tick, GEMM_0 x-index prefetch.

#define NBLK  128
#define NTHR  640
#define ROWS  8
#define TT    1024
#define LL    10
#define HID   32
#define VOC   256
#define LST   36
#define RL    (ROWS*LST)
#define DEPTH 8
#define NTICK 275

typedef unsigned long long ull;

__device__ __forceinline__ void ffma2(ull &d, ull a, ull b) {
    asm("fma.rn.f32x2 %0, %1, %2, %0;" : "+l"(d) : "l"(a), "l"(b));
}
__device__ __forceinline__ float f2red(ull a) {
    float lo, hi;
    asm("mov.b64 {%0, %1}, %2;" : "=f"(lo), "=f"(hi) : "l"(a));
    return lo + hi;
}
// tanh(x) = 1 - 2/(exp(2x)+1): ex2(x*2log2e) -> rcp(e+1) -> fma(-2,r,1).
__device__ __forceinline__ float tanh_fast(float x) {
    float e;
    asm("ex2.approx.f32 %0, %1;" : "=f"(e) : "f"(x * 2.885390082f));
    float r;
    asm("rcp.approx.f32 %0, %1;" : "=f"(r) : "f"(e + 1.0f));
    return fmaf(-2.0f, r, 1.0f);
}

__global__ void __launch_bounds__(NTHR, 1)
charrnn_kernel(const int*   __restrict__ x,
               const float* __restrict__ emb,
               const float* __restrict__ W_ih,
               const float* __restrict__ W_hh,
               const float* __restrict__ b_ih,
               const float* __restrict__ b_hh,
               const float* __restrict__ W_fc,
               const float* __restrict__ b_fc,
               float*       __restrict__ out)
{
    extern __shared__ float smem[];
    float* sh  = smem;                        // h rings [LL][DEPTH][ROWS][LST]
    float* sz  = smem + LL * DEPTH * RL;      // z rings [LL][DEPTH][ROWS][LST]
    float* sxs = sz   + LL * DEPTH * RL;      // GEMM_0 stage [4][ROWS][LST]

    const int tid  = threadIdx.x;
    const int wid  = tid >> 5;
    const int lane = tid & 31;
    const int row0 = blockIdx.x * ROWS;

    for (int i = tid; i < LL * DEPTH * RL; i += NTHR) sh[i] = 0.0f;

    const bool isRec = (wid < 10);
    const int  l     = isRec ? wid : (wid - 10);

    float*       hown = sh + l * DEPTH * RL;
    const float* hup  = (l > 0) ? (sh + (l - 1) * DEPTH * RL) : sxs;
    float*       zl   = sz + l * DEPTH * RL;

    const int half = lane >> 4;       // row half (0: rows 0-3, 1: rows 4-7)
    const int rb   = half * 4;
    const int n0   = lane & 15;       // owned neurons n0, n0+16
    const int n1   = n0 + 16;

    if (isRec) {
        // ======================= REC warp: h = tanh(z + Whh.h) =======================
        ull whh0[16], whh1[16];
        {
            const ulonglong2* p = (const ulonglong2*)(W_hh + (l * HID + n0) * HID);
            #pragma unroll
            for (int q = 0; q < 8; ++q) { ulonglong2 v = p[q]; whh0[2*q] = v.x; whh0[2*q+1] = v.y; }
            p = (const ulonglong2*)(W_hh + (l * HID + n1) * HID);
            #pragma unroll
            for (int q = 0; q < 8; ++q) { ulonglong2 v = p[q]; whh1[2*q] = v.x; whh1[2*q+1] = v.y; }
        }
        __syncthreads();

        for (int v = 0; v < NTICK; ++v) {
            const int t0 = 4 * (v - 2 * l - 1);
            if (t0 >= 0 && t0 < TT) {
                #pragma unroll
                for (int st = 0; st < 4; ++st) {
                    const int t = t0 + st;
                    const float* hb   = hown + ((t - 1) & (DEPTH-1)) * RL;
                    const float* zrow = zl   + (t & (DEPTH-1)) * RL;
                    float*       ob   = hown + (t & (DEPTH-1)) * RL;

                    #pragma unroll
                    for (int g = 0; g < 2; ++g) {
                        const int rA = rb + 2*g;
                        const int rB = rA + 1;
                        // hoisted scalar z loads (latency hides under FMA chain)
                        const float zA0 = zrow[rA * LST + n0];
                        const float zA1 = zrow[rA * LST + n1];
                        const float zB0 = zrow[rB * LST + n0];
                        const float zB1 = zrow[rB * LST + n1];
                        ull a00 = 0ull, a01 = 0ull, a10 = 0ull, a11 = 0ull;
                        #pragma unroll
                        for (int q = 0; q < 8; ++q) {
                            ulonglong2 vA = *(const ulonglong2*)(hb + rA * LST + q * 4);
                            ulonglong2 vB = *(const ulonglong2*)(hb + rB * LST + q * 4);
                            ffma2(a00, whh0[2*q], vA.x); ffma2(a00, whh0[2*q+1], vA.y);
                            ffma2(a01, whh1[2*q], vA.x); ffma2(a01, whh1[2*q+1], vA.y);
                            ffma2(a10, whh0[2*q], vB.x); ffma2(a10, whh0[2*q+1], vB.y);
                            ffma2(a11, whh1[2*q], vB.x); ffma2(a11, whh1[2*q+1], vB.y);
                        }
                        ob[rA * LST + n0] = tanh_fast(f2red(a00) + zA0);
                        ob[rA * LST + n1] = tanh_fast(f2red(a01) + zA1);
                        ob[rB * LST + n0] = tanh_fast(f2red(a10) + zB0);
                        ob[rB * LST + n1] = tanh_fast(f2red(a11) + zB1);
                    }
                    __syncwarp();
                }
            }
            __syncthreads();
        }
    } else {
        // ======================= GEMM warp: z = Wih.x + bias =======================
        ull wih0[16], wih1[16];
        {
            const ulonglong2* p = (const ulonglong2*)(W_ih + (l * HID + n0) * HID);
            #pragma unroll
            for (int q = 0; q < 8; ++q) { ulonglong2 v = p[q]; wih0[2*q] = v.x; wih0[2*q+1] = v.y; }
            p = (const ulonglong2*)(W_ih + (l * HID + n1) * HID);
            #pragma unroll
            for (int q = 0; q < 8; ++q) { ulonglong2 v = p[q]; wih1[2*q] = v.x; wih1[2*q+1] = v.y; }
        }
        const float bias0 = __ldg(&b_ih[l * HID + n0]) + __ldg(&b_hh[l * HID + n0]);
        const float bias1 = __ldg(&b_ih[l * HID + n1]) + __ldg(&b_hh[l * HID + n1]);

        int4 xi = make_int4(0, 0, 0, 0);
        if (l == 0 && lane < ROWS)
            xi = *(const int4*)(x + (row0 + lane) * TT);

        __syncthreads();

        for (int v = 0; v < NTICK; ++v) {
            const int t0 = 4 * (v - 2 * l);
            if (t0 >= 0 && t0 < TT) {
                if (l == 0) {
                    #pragma unroll
                    for (int r = 0; r < ROWS; ++r) {
                        const int ix = __shfl_sync(0xffffffffu, xi.x, r);
                        const int iy = __shfl_sync(0xffffffffu, xi.y, r);
                        const int iz = __shfl_sync(0xffffffffu, xi.z, r);
                        const int iw = __shfl_sync(0xffffffffu, xi.w, r);
                        sxs[0 * RL + r * LST + lane] = __ldg(&emb[ix * HID + lane]);
                        sxs[1 * RL + r * LST + lane] = __ldg(&emb[iy * HID + lane]);
                        sxs[2 * RL + r * LST + lane] = __ldg(&emb[iz * HID + lane]);
                        sxs[3 * RL + r * LST + lane] = __ldg(&emb[iw * HID + lane]);
                    }
                    if (lane < ROWS && t0 + 4 < TT)
                        xi = *(const int4*)(x + (row0 + lane) * TT + t0 + 4);
                    __syncwarp();
                }
                #pragma unroll
                for (int st = 0; st < 4; ++st) {
                    const int t = t0 + st;
                    const float* inb = (l == 0) ? (sxs + st * RL)
                                                : (hup + (t & (DEPTH-1)) * RL);
                    float* zo = zl + (t & (DEPTH-1)) * RL;

                    #pragma unroll
                    for (int g = 0; g < 2; ++g) {
                        const int rA = rb + 2*g;
                        const int rB = rA + 1;
                        ull a00 = 0ull, a01 = 0ull, a10 = 0ull, a11 = 0ull;
                        #pragma unroll
                        for (int q = 0; q < 8; ++q) {
                            ulonglong2 vA = *(const ulonglong2*)(inb + rA * LST + q * 4);
                            ulonglong2 vB = *(const ulonglong2*)(inb + rB * LST + q * 4);
                            ffma2(a00, wih0[2*q], vA.x); ffma2(a00, wih0[2*q+1], vA.y);
                            ffma2(a01, wih1[2*q], vA.x); ffma2(a01, wih1[2*q+1], vA.y);
                            ffma2(a10, wih0[2*q], vB.x); ffma2(a10, wih0[2*q+1], vB.y);
                            ffma2(a11, wih1[2*q], vB.x); ffma2(a11, wih1[2*q+1], vB.y);
                        }
                        zo[rA * LST + n0] = f2red(a00) + bias0;
                        zo[rA * LST + n1] = f2red(a01) + bias1;
                        zo[rB * LST + n0] = f2red(a10) + bias0;
                        zo[rB * LST + n1] = f2red(a11) + bias1;
                    }
                }
            }
            __syncthreads();
        }
    }

    __syncthreads();

    // ---- final FC: out = h9(1023) @ W_fc^T + b_fc ; slot 1023&7 = 7 ----
    const float* h9 = sh + ((LL - 1) * DEPTH + 7) * RL;
    for (int i = tid; i < ROWS * VOC; i += NTHR) {
        const int r  = i >> 8;
        const int vv = i & (VOC - 1);
        const float4* wfc = (const float4*)(W_fc + vv * HID);
        const float*  hr  = h9 + r * LST;
        float sum = __ldg(&b_fc[vv]);
        #pragma unroll
        for (int q = 0; q < 8; ++q) {
            float4 aw = wfc[q];
            sum += aw.x * hr[q*4+0] + aw.y * hr[q*4+1] + aw.z * hr[q*4+2] + aw.w * hr[q*4+3];
        }
        out[(row0 + r) * VOC + vv] = sum;
    }
}

extern "C" void kernel_launch(void* const* d_in, const int* in_sizes, int n_in,
                              void* d_out, int out_size)
{
    const int*   x    = (const int*)  d_in[0];
    const float* emb  = (const float*)d_in[1];
    const float* W_ih = (const float*)d_in[2];
    const float* W_hh = (const float*)d_in[3];
    const float* b_ih = (const float*)d_in[4];
    const float* b_hh = (const float*)d_in[5];
    const float* W_fc = (const float*)d_in[6];
    const float* b_fc = (const float*)d_in[7];
    float* out = (float*)d_out;

    const int shbytes = (2 * LL * DEPTH + 4) * RL * (int)sizeof(float);  // 188928
    cudaFuncSetAttribute(charrnn_kernel,
                         cudaFuncAttributeMaxDynamicSharedMemorySize, shbytes);
    charrnn_kernel<<<NBLK, NTHR, shbytes>>>(x, emb, W_ih, W_hh, b_ih, b_hh,
                                            W_fc, b_fc, out);
}

// round 17
// speedup vs baseline: 1.1074x; 1.0198x over previous
#include <cuda_runtime.h>
#include <cstdint>

// CharRNN on GB300 (sm_103a), round 16 = R12 (best, 1245us) + accumulator-
// initialized bias/z (deletes the terminal FADD per output in both roles).
// tanh stays the R12 __expf/__fdividef form (the alu-clean variant).
// 128 blocks x 640 threads. wids 0..9 = REC layers, 10..19 = GEMM layers.
// Lane owns neurons (n0, n0+16) for its 4-row half; 4 steps/tick; depth-8
// h/z rings; scalar z; one __syncthreads per tick; GEMM_0 x-index prefetch.

#define NBLK  128
#define NTHR  640
#define ROWS  8
#define TT    1024
#define LL    10
#define HID   32
#define VOC   256
#define LST   36
#define RL    (ROWS*LST)
#define DEPTH 8
#define NTICK 275

typedef unsigned long long ull;

__device__ __forceinline__ void ffma2(ull &d, ull a, ull b) {
    asm("fma.rn.f32x2 %0, %1, %2, %0;" : "+l"(d) : "l"(a), "l"(b));
}
__device__ __forceinline__ float f2red(ull a) {
    float lo, hi;
    asm("mov.b64 {%0, %1}, %2;" : "=f"(lo), "=f"(hi) : "l"(a));
    return lo + hi;
}
__device__ __forceinline__ ull packf2(float lo, float hi) {
    ull r;
    asm("mov.b64 %0, {%1, %2};" : "=l"(r) : "f"(lo), "f"(hi));
    return r;
}
// tanh(x) = 1 - 2/(exp(2x)+1).  __expf -> MUFU.EX2, __fdividef -> MUFU.RCP.
__device__ __forceinline__ float tanh_fast(float x) {
    float e = __expf(2.0f * x);
    return 1.0f - __fdividef(2.0f, e + 1.0f);
}

__global__ void __launch_bounds__(NTHR, 1)
charrnn_kernel(const int*   __restrict__ x,
               const float* __restrict__ emb,
               const float* __restrict__ W_ih,
               const float* __restrict__ W_hh,
               const float* __restrict__ b_ih,
               const float* __restrict__ b_hh,
               const float* __restrict__ W_fc,
               const float* __restrict__ b_fc,
               float*       __restrict__ out)
{
    extern __shared__ float smem[];
    float* sh  = smem;                        // h rings [LL][DEPTH][ROWS][LST]
    float* sz  = smem + LL * DEPTH * RL;      // z rings [LL][DEPTH][ROWS][LST]
    float* sxs = sz   + LL * DEPTH * RL;      // GEMM_0 stage [4][ROWS][LST]

    const int tid  = threadIdx.x;
    const int wid  = tid >> 5;
    const int lane = tid & 31;
    const int row0 = blockIdx.x * ROWS;

    for (int i = tid; i < LL * DEPTH * RL; i += NTHR) sh[i] = 0.0f;

    const bool isRec = (wid < 10);
    const int  l     = isRec ? wid : (wid - 10);

    float*       hown = sh + l * DEPTH * RL;
    const float* hup  = (l > 0) ? (sh + (l - 1) * DEPTH * RL) : sxs;
    float*       zl   = sz + l * DEPTH * RL;

    const int half = lane >> 4;       // row half (0: rows 0-3, 1: rows 4-7)
    const int rb   = half * 4;
    const int n0   = lane & 15;       // owned neurons n0, n0+16
    const int n1   = n0 + 16;

    if (isRec) {
        // ======================= REC warp: h = tanh(z + Whh.h) =======================
        ull whh0[16], whh1[16];
        {
            const ulonglong2* p = (const ulonglong2*)(W_hh + (l * HID + n0) * HID);
            #pragma unroll
            for (int q = 0; q < 8; ++q) { ulonglong2 v = p[q]; whh0[2*q] = v.x; whh0[2*q+1] = v.y; }
            p = (const ulonglong2*)(W_hh + (l * HID + n1) * HID);
            #pragma unroll
            for (int q = 0; q < 8; ++q) { ulonglong2 v = p[q]; whh1[2*q] = v.x; whh1[2*q+1] = v.y; }
        }
        __syncthreads();

        for (int v = 0; v < NTICK; ++v) {
            const int t0 = 4 * (v - 2 * l - 1);
            if (t0 >= 0 && t0 < TT) {
                #pragma unroll
                for (int st = 0; st < 4; ++st) {
                    const int t = t0 + st;
                    const float* hb   = hown + ((t - 1) & (DEPTH-1)) * RL;
                    const float* zrow = zl   + (t & (DEPTH-1)) * RL;
                    float*       ob   = hown + (t & (DEPTH-1)) * RL;

                    #pragma unroll
                    for (int g = 0; g < 2; ++g) {
                        const int rA = rb + 2*g;
                        const int rB = rA + 1;
                        // z seeds the accumulator lo-half: terminal FADD deleted
                        ull a00 = packf2(zrow[rA * LST + n0], 0.0f);
                        ull a01 = packf2(zrow[rA * LST + n1], 0.0f);
                        ull a10 = packf2(zrow[rB * LST + n0], 0.0f);
                        ull a11 = packf2(zrow[rB * LST + n1], 0.0f);
                        #pragma unroll
                        for (int q = 0; q < 8; ++q) {
                            ulonglong2 vA = *(const ulonglong2*)(hb + rA * LST + q * 4);
                            ulonglong2 vB = *(const ulonglong2*)(hb + rB * LST + q * 4);
                            ffma2(a00, whh0[2*q], vA.x); ffma2(a00, whh0[2*q+1], vA.y);
                            ffma2(a01, whh1[2*q], vA.x); ffma2(a01, whh1[2*q+1], vA.y);
                            ffma2(a10, whh0[2*q], vB.x); ffma2(a10, whh0[2*q+1], vB.y);
                            ffma2(a11, whh1[2*q], vB.x); ffma2(a11, whh1[2*q+1], vB.y);
                        }
                        ob[rA * LST + n0] = tanh_fast(f2red(a00));
                        ob[rA * LST + n1] = tanh_fast(f2red(a01));
                        ob[rB * LST + n0] = tanh_fast(f2red(a10));
                        ob[rB * LST + n1] = tanh_fast(f2red(a11));
                    }
                    __syncwarp();
                }
            }
            __syncthreads();
        }
    } else {
        // ======================= GEMM warp: z = Wih.x + bias =======================
        ull wih0[16], wih1[16];
        {
            const ulonglong2* p = (const ulonglong2*)(W_ih + (l * HID + n0) * HID);
            #pragma unroll
            for (int q = 0; q < 8; ++q) { ulonglong2 v = p[q]; wih0[2*q] = v.x; wih0[2*q+1] = v.y; }
            p = (const ulonglong2*)(W_ih + (l * HID + n1) * HID);
            #pragma unroll
            for (int q = 0; q < 8; ++q) { ulonglong2 v = p[q]; wih1[2*q] = v.x; wih1[2*q+1] = v.y; }
        }
        const float bias0 = __ldg(&b_ih[l * HID + n0]) + __ldg(&b_hh[l * HID + n0]);
        const float bias1 = __ldg(&b_ih[l * HID + n1]) + __ldg(&b_hh[l * HID + n1]);
        const ull   bp0   = packf2(bias0, 0.0f);   // loop-invariant acc seeds
        const ull   bp1   = packf2(bias1, 0.0f);

        int4 xi = make_int4(0, 0, 0, 0);
        if (l == 0 && lane < ROWS)
            xi = *(const int4*)(x + (row0 + lane) * TT);

        __syncthreads();

        for (int v = 0; v < NTICK; ++v) {
            const int t0 = 4 * (v - 2 * l);
            if (t0 >= 0 && t0 < TT) {
                if (l == 0) {
                    #pragma unroll
                    for (int r = 0; r < ROWS; ++r) {
                        const int ix = __shfl_sync(0xffffffffu, xi.x, r);
                        const int iy = __shfl_sync(0xffffffffu, xi.y, r);
                        const int iz = __shfl_sync(0xffffffffu, xi.z, r);
                        const int iw = __shfl_sync(0xffffffffu, xi.w, r);
                        sxs[0 * RL + r * LST + lane] = __ldg(&emb[ix * HID + lane]);
                        sxs[1 * RL + r * LST + lane] = __ldg(&emb[iy * HID + lane]);
                        sxs[2 * RL + r * LST + lane] = __ldg(&emb[iz * HID + lane]);
                        sxs[3 * RL + r * LST + lane] = __ldg(&emb[iw * HID + lane]);
                    }
                    if (lane < ROWS && t0 + 4 < TT)
                        xi = *(const int4*)(x + (row0 + lane) * TT + t0 + 4);
                    __syncwarp();
                }
                #pragma unroll
                for (int st = 0; st < 4; ++st) {
                    const int t = t0 + st;
                    const float* inb = (l == 0) ? (sxs + st * RL)
                                                : (hup + (t & (DEPTH-1)) * RL);
                    float* zo = zl + (t & (DEPTH-1)) * RL;

                    #pragma unroll
                    for (int g = 0; g < 2; ++g) {
                        const int rA = rb + 2*g;
                        const int rB = rA + 1;
                        ull a00 = bp0, a01 = bp1, a10 = bp0, a11 = bp1;
                        #pragma unroll
                        for (int q = 0; q < 8; ++q) {
                            ulonglong2 vA = *(const ulonglong2*)(inb + rA * LST + q * 4);
                            ulonglong2 vB = *(const ulonglong2*)(inb + rB * LST + q * 4);
                            ffma2(a00, wih0[2*q], vA.x); ffma2(a00, wih0[2*q+1], vA.y);
                            ffma2(a01, wih1[2*q], vA.x); ffma2(a01, wih1[2*q+1], vA.y);
                            ffma2(a10, wih0[2*q], vB.x); ffma2(a10, wih0[2*q+1], vB.y);
                            ffma2(a11, wih1[2*q], vB.x); ffma2(a11, wih1[2*q+1], vB.y);
                        }
                        zo[rA * LST + n0] = f2red(a00);
                        zo[rA * LST + n1] = f2red(a01);
                        zo[rB * LST + n0] = f2red(a10);
                        zo[rB * LST + n1] = f2red(a11);
                    }
                }
            }
            __syncthreads();
        }
    }

    __syncthreads();

    // ---- final FC: out = h9(1023) @ W_fc^T + b_fc ; slot 1023&7 = 7 ----
    const float* h9 = sh + ((LL - 1) * DEPTH + 7) * RL;
    for (int i = tid; i < ROWS * VOC; i += NTHR) {
        const int r  = i >> 8;
        const int vv = i & (VOC - 1);
        const float4* wfc = (const float4*)(W_fc + vv * HID);
        const float*  hr  = h9 + r * LST;
        float sum = __ldg(&b_fc[vv]);
        #pragma unroll
        for (int q = 0; q < 8; ++q) {
            float4 aw = wfc[q];
            sum += aw.x * hr[q*4+0] + aw.y * hr[q*4+1] + aw.z * hr[q*4+2] + aw.w * hr[q*4+3];
        }
        out[(row0 + r) * VOC + vv] = sum;
    }
}

extern "C" void kernel_launch(void* const* d_in, const int* in_sizes, int n_in,
                              void* d_out, int out_size)
{
    const int*   x    = (const int*)  d_in[0];
    const float* emb  = (const float*)d_in[1];
    const float* W_ih = (const float*)d_in[2];
    const float* W_hh = (const float*)d_in[3];
    const float* b_ih = (const float*)d_in[4];
    const float* b_hh = (const float*)d_in[5];
    const float* W_fc = (const float*)d_in[6];
    const float* b_fc = (const float*)d_in[7];
    float* out = (float*)d_out;

    const int shbytes = (2 * LL * DEPTH + 4) * RL * (int)sizeof(float);  // 188928
    cudaFuncSetAttribute(charrnn_kernel,
                         cudaFuncAttributeMaxDynamicSharedMemorySize, shbytes);
    charrnn_kernel<<<NBLK, NTHR, shbytes>>>(x, emb, W_ih, W_hh, b_ih, b_hh,
                                            W_fc, b_fc, out);
}